// round 11
// baseline (speedup 1.0000x reference)
#include <cuda_runtime.h>
#include <cuda_fp16.h>
#include <cstdint>

#define Ln    6368
#define Tt    128
#define H1n   2133
#define H2n   4250
#define NT    398          // 16-row tiles: 6368/16
#define TPC   32           // fragment-tiles per chunk (16 KB)
#define CHB   (TPC * 512)  // 16384 B
#define NCH   13           // ceil(398/32)
#define NSTG  3            // ring stages
#define THS   6376         // padded theta smem stride (halves) -> conflict-free LDS

// dynamic smem layout (bytes)
#define SM_TH    0                    // fp16 theta 4*THS*2 = 51008 (slot 51200)
#define SM_EBUF  51200                // 3 stages * 16384 = 49152
#define SM_MBAR  (51200 + 49152)      // 3 mbarriers (pad 128)
#define SM_DYN   (SM_MBAR + 128)      // 100480

// ---------------- device state ----------------
__device__ __align__(16) uint4  g_Epk[(size_t)NT * NT * 32];   // E fragments, 81 MB
__device__ __align__(16) float  g_theta[2][Ln * 4];            // fp32 theta [j][b]
__device__ __align__(16) __half g_thh[2][4][Ln];               // fp16 theta [b][j]
__device__ __align__(16) float  g_h1[H1n * 4];
__device__ __align__(16) float  g_h2[H2n * 4];
__device__ __align__(16) float  g_xhat[Tt][4][16];

// ---------------- helpers ----------------
__device__ __forceinline__ uint32_t s2u(const void* p) {
    uint32_t a;
    asm("{ .reg .u64 t; cvta.to.shared.u64 t, %1; cvt.u32.u64 %0, t; }" : "=r"(a) : "l"(p));
    return a;
}
#define MBAR_INIT(a, n) asm volatile("mbarrier.init.shared.b64 [%0], %1;" :: "r"(a), "r"(n) : "memory")
#define MBAR_EXPECT(a, b) asm volatile("mbarrier.arrive.expect_tx.shared.b64 _, [%0], %1;" :: "r"(a), "r"(b) : "memory")
#define MBAR_WAIT(a, p) asm volatile( \
    "{\n\t.reg .pred P1;\nWL_%=:\n\t" \
    "mbarrier.try_wait.parity.acquire.cta.shared::cta.b64 P1, [%0], %1, 0x989680;\n\t" \
    "@P1 bra.uni WD_%=;\n\tbra.uni WL_%=;\nWD_%=:\n\t}" \
    :: "r"(a), "r"(p) : "memory")
#define BULK_CP_EL(dst, src, bytes, mb, pol) \
    asm volatile("cp.async.bulk.shared::cta.global.mbarrier::complete_tx::bytes.L2::cache_hint " \
                 "[%0], [%1], %2, [%3], %4;" \
                 :: "r"(dst), "l"(src), "r"(bytes), "r"(mb), "l"(pol) : "memory")

// ---------------- E conversion + fragment repack ----------------
__global__ void cvt_E_pack(const float* __restrict__ A) {
    size_t idx = (size_t)blockIdx.x * blockDim.x + threadIdx.x;
    if (idx >= (size_t)NT * NT * 32) return;
    int lane = (int)(idx & 31);
    size_t tIdx = idx >> 5;
    int rt = (int)(tIdx / NT), jt = (int)(tIdx % NT);
    int r0 = rt * 16 + (lane >> 2);
    int c0 = jt * 16 + (lane & 3) * 2;
    const float* Ar0 = A + (size_t)r0 * Ln;
    const float* Ar8 = A + (size_t)(r0 + 8) * Ln;
    float2 p00 = *reinterpret_cast<const float2*>(Ar0 + c0);
    float2 p10 = *reinterpret_cast<const float2*>(Ar8 + c0);
    float2 p01 = *reinterpret_cast<const float2*>(Ar0 + c0 + 8);
    float2 p11 = *reinterpret_cast<const float2*>(Ar8 + c0 + 8);
    if (r0 == c0)         p00.x -= 0.999f;
    if (r0 == c0 + 1)     p00.y -= 0.999f;
    if (r0 + 8 == c0)     p10.x -= 0.999f;
    if (r0 + 8 == c0 + 1) p10.y -= 0.999f;
    if (r0 == c0 + 8)     p01.x -= 0.999f;
    if (r0 == c0 + 9)     p01.y -= 0.999f;
    if (r0 + 8 == c0 + 8) p11.x -= 0.999f;
    if (r0 + 8 == c0 + 9) p11.y -= 0.999f;
    __half2 h0 = __floats2half2_rn(p00.x, p00.y);
    __half2 h1 = __floats2half2_rn(p10.x, p10.y);
    __half2 h2 = __floats2half2_rn(p01.x, p01.y);
    __half2 h3 = __floats2half2_rn(p11.x, p11.y);
    uint4 v;
    v.x = *reinterpret_cast<unsigned*>(&h0);
    v.y = *reinterpret_cast<unsigned*>(&h1);
    v.z = *reinterpret_cast<unsigned*>(&h2);
    v.w = *reinterpret_cast<unsigned*>(&h3);
    g_Epk[idx] = v;
}

// ---------------- init MLP ----------------
__global__ void mlp1_kernel(const float* __restrict__ W1, const float* __restrict__ b1,
                            const float* __restrict__ xs) {
    int t = blockIdx.x * blockDim.x + threadIdx.x;
    if (t >= H1n * 4) return;
    int row = t >> 2, b = t & 3;
    float a = b1[row];
    const float* x0 = xs + (size_t)b * Tt * 16;
#pragma unroll
    for (int d = 0; d < 16; d++) a = fmaf(W1[row * 16 + d], x0[d], a);
    g_h1[row * 4 + b] = fmaxf(a, 0.0f);
}

__global__ void matvec4(const float* __restrict__ W, const float* __restrict__ bias,
                        const float* __restrict__ xin, float* __restrict__ yout,
                        int rows, int K, int relu) {
    int w = (blockIdx.x * blockDim.x + threadIdx.x) >> 5;
    int lane = threadIdx.x & 31;
    if (w >= rows) return;
    const float* Wr = W + (size_t)w * K;
    float a0 = 0.f, a1 = 0.f, a2 = 0.f, a3 = 0.f;
#pragma unroll 4
    for (int j = lane; j < K; j += 32) {
        float wv = Wr[j];
        float4 xv = reinterpret_cast<const float4*>(xin)[j];
        a0 = fmaf(wv, xv.x, a0); a1 = fmaf(wv, xv.y, a1);
        a2 = fmaf(wv, xv.z, a2); a3 = fmaf(wv, xv.w, a3);
    }
#pragma unroll
    for (int m = 16; m > 0; m >>= 1) {
        a0 += __shfl_xor_sync(0xffffffffu, a0, m);
        a1 += __shfl_xor_sync(0xffffffffu, a1, m);
        a2 += __shfl_xor_sync(0xffffffffu, a2, m);
        a3 += __shfl_xor_sync(0xffffffffu, a3, m);
    }
    if (lane == 0) {
        float bb = bias[w];
        a0 += bb; a1 += bb; a2 += bb; a3 += bb;
        if (relu) {
            a0 = fmaxf(a0, 0.f); a1 = fmaxf(a1, 0.f);
            a2 = fmaxf(a2, 0.f); a3 = fmaxf(a3, 0.f);
        }
        reinterpret_cast<float4*>(yout)[w] = make_float4(a0, a1, a2, a3);
    }
}

__global__ void cvt_th0() {
    int t = blockIdx.x * blockDim.x + threadIdx.x;
    if (t >= Ln * 4) return;
    int row = t >> 2, b = t & 3;
    g_thh[0][b][row] = __float2half(g_theta[0][row * 4 + b]);
}

// ---------------- tiny root MLP ----------------
__device__ void root_apply(int j, const float* __restrict__ th,
                           const float* __restrict__ ts, float* __restrict__ out) {
    __shared__ float rh0[4][64];
    __shared__ float rh1[4][64];
    int tid = threadIdx.x;
    int b = tid >> 6, k = tid & 63;
    float tj  = ts[b * Tt + j];
    float tin = (j == 0) ? tj : (2.0f * tj - ts[b * Tt + j - 1]);
    float h = fmaf(th[k * 4 + b], tin, th[(64 + k) * 4 + b]);
    rh0[b][k] = fmaxf(h, 0.0f);
    __syncthreads();
    float a = th[(4224 + k) * 4 + b];
#pragma unroll 8
    for (int c = 0; c < 64; c++)
        a = fmaf(th[(128 + k * 64 + c) * 4 + b], rh0[b][c], a);
    rh1[b][k] = fmaxf(a, 0.0f);
    __syncthreads();
    if (k < 32) {
        float o = th[(6336 + k) * 4 + b];
#pragma unroll 8
        for (int c = 0; c < 64; c++)
            o = fmaf(th[(4288 + k * 64 + c) * 4 + b], rh1[b][c], o);
        float v;
        if (k < 16) {
            v = tanhf(o);
            g_xhat[j][b][k] = v;
        } else {
            v = fmaxf(o, 0.0f) + log1pf(expf(-fabsf(o)));
        }
        out[((size_t)b * Tt + j) * 32 + k] = v;
    }
}

// ---------------- per-step kernel: block-chunked TMA ring ----------------
// Block 0: root MLP for step i-1. Blocks 1..398: one 16-row tile.
// One producer thread streams the tile's contiguous 199KB of E in 16KB chunks
// through a 3-stage ring; 8 warps consume each chunk (K-split by lt mod 8).
__global__ void __launch_bounds__(256, 2) step_kernel(int i, const float* __restrict__ xs,
                                                      const float* __restrict__ ts,
                                                      const float* __restrict__ Bm,
                                                      float* __restrict__ out) {
    const float* thin = g_theta[i & 1];
    if (blockIdx.x == 0) {
        if (i >= 1) root_apply(i - 1, thin, ts, out);
        return;
    }
    extern __shared__ __align__(1024) char dsm[];
    __half* th_s = reinterpret_cast<__half*>(dsm);
    uint32_t smem_base = s2u(dsm);
    uint32_t mbar_base = smem_base + SM_MBAR;
    uint32_t ebuf = smem_base + SM_EBUF;

    __shared__ float sacc[8][16][8];
    __shared__ float sdiff[17 * 4];

    int tid = threadIdx.x, lane = tid & 31, w = tid >> 5;
    int rt = blockIdx.x - 1;
    const char* esrc = reinterpret_cast<const char*>(g_Epk) + (size_t)rt * NT * 512;

    uint64_t pol;
    asm("createpolicy.fractional.L2::evict_last.b64 %0, 1.0;" : "=l"(pol));

    // stage fp16 theta into padded smem (conflict-free stride)
    {
        const uint4* src = reinterpret_cast<const uint4*>(&g_thh[i & 1][0][0]);
        for (int k = tid; k < 4 * (Ln / 8); k += 256) {
            int b = k / (Ln / 8), q = k - b * (Ln / 8);
            *reinterpret_cast<uint4*>(th_s + b * THS + q * 8) = src[k];
        }
    }
    if (tid < NSTG) MBAR_INIT(mbar_base + tid * 8, 1);
    if (tid < 68) {
        int c = tid >> 2, b = tid & 3;
        float d;
        if (c == 0) {
            d = (i == 0) ? 0.0f : ts[b * Tt + i] - ts[b * Tt + i - 1];
        } else {
            float xt = xs[((size_t)b * Tt + i) * 16 + (c - 1)];
            float xp = (i < 2) ? xs[(size_t)b * Tt * 16 + (c - 1)]
                               : g_xhat[i - 2][b][c - 1];
            d = xt - xp;
        }
        sdiff[c * 4 + b] = d;
    }
    __syncthreads();

    // prologue: fill all ring stages
    if (tid == 0) {
        asm volatile("fence.proxy.async.shared::cta;" ::: "memory");
#pragma unroll
        for (int s = 0; s < NSTG; s++) {
            int cb = s * TPC;
            unsigned bytes = (unsigned)(min(TPC, NT - cb) * 512);
            MBAR_EXPECT(mbar_base + s * 8, bytes);
            BULK_CP_EL(ebuf + s * CHB, esrc + (size_t)cb * 512, bytes, mbar_base + s * 8, pol);
        }
    }

    int n = lane >> 2, k0 = (lane & 3) * 2;
    const __half* bn = th_s + n * THS;
    bool bvalid = (n < 4);

    float c0 = 0.f, c1 = 0.f, c2 = 0.f, c3 = 0.f;
    for (int c = 0; c < NCH; c++) {
        int s = c % NSTG, ph = (c / NSTG) & 1;
        MBAR_WAIT(mbar_base + s * 8, ph);
        int cb = c * TPC;
        int tic = min(TPC, NT - cb);
        uint32_t ebase = ebuf + s * CHB + lane * 16;
#pragma unroll
        for (int u = 0; u < TPC / 8; u++) {        // lt = w, w+8, w+16, w+24
            int lt = w + u * 8;
            if (lt >= tic) break;
            uint4 af;
            asm volatile("ld.shared.v4.u32 {%0,%1,%2,%3}, [%4];"
                         : "=r"(af.x), "=r"(af.y), "=r"(af.z), "=r"(af.w)
                         : "r"(ebase + lt * 512));
            unsigned b0 = 0u, b1 = 0u;
            if (bvalid) {
                int jj = (cb + lt) * 16 + k0;
                b0 = *reinterpret_cast<const unsigned*>(bn + jj);
                b1 = *reinterpret_cast<const unsigned*>(bn + jj + 8);
            }
            asm volatile(
                "mma.sync.aligned.m16n8k16.row.col.f32.f16.f16.f32 "
                "{%0,%1,%2,%3}, {%4,%5,%6,%7}, {%8,%9}, {%0,%1,%2,%3};"
                : "+f"(c0), "+f"(c1), "+f"(c2), "+f"(c3)
                : "r"(af.x), "r"(af.y), "r"(af.z), "r"(af.w), "r"(b0), "r"(b1));
        }
        __syncthreads();                           // stage s fully consumed
        if (tid == 0) {
            int nc = c + NSTG;
            if (nc < NCH) {
                asm volatile("fence.proxy.async.shared::cta;" ::: "memory");
                int nb = nc * TPC;
                unsigned bytes = (unsigned)(min(TPC, NT - nb) * 512);
                MBAR_EXPECT(mbar_base + s * 8, bytes);
                BULK_CP_EL(ebuf + s * CHB, esrc + (size_t)nb * 512, bytes, mbar_base + s * 8, pol);
            }
        }
    }

    {
        int r = lane >> 2, cc = (lane & 3) * 2;
        sacc[w][r][cc]         = c0;
        sacc[w][r][cc + 1]     = c1;
        sacc[w][r + 8][cc]     = c2;
        sacc[w][r + 8][cc + 1] = c3;
    }
    __syncthreads();

    if (tid < 64) {
        int rr = tid >> 2, b = tid & 3;
        float v = 0.f;
#pragma unroll
        for (int kw = 0; kw < 8; kw++) v += sacc[kw][rr][b];
        int row = rt * 16 + rr;
        float y = fmaf(0.999f, thin[row * 4 + b], v);
        const float* bmr = Bm + (size_t)row * 17;
#pragma unroll
        for (int c = 0; c < 17; c++) y = fmaf(bmr[c], sdiff[c * 4 + b], y);
        g_theta[(i + 1) & 1][row * 4 + b] = y;
        g_thh[(i + 1) & 1][b][row] = __float2half(y);
    }
}

// ---------------- final root for step T-1 ----------------
__global__ void root_final(const float* __restrict__ ts, float* __restrict__ out) {
    root_apply(Tt - 1, g_theta[Tt & 1], ts, out);
}

// ---------------- launch ----------------
extern "C" void kernel_launch(void* const* d_in, const int* in_sizes, int n_in,
                              void* d_out, int out_size) {
    const float* xs = (const float*)d_in[0];
    const float* ts = (const float*)d_in[1];
    const float* A  = (const float*)d_in[2];
    const float* Bm = (const float*)d_in[3];
    const float* W1 = (const float*)d_in[4];
    const float* b1 = (const float*)d_in[5];
    const float* W2 = (const float*)d_in[6];
    const float* b2 = (const float*)d_in[7];
    const float* W3 = (const float*)d_in[8];
    const float* b3 = (const float*)d_in[9];
    // d_in[10] = seed: dead (FORCING_PROB == 1.0)
    float* out = (float*)d_out;

    static bool attr_done = false;
    if (!attr_done) {
        cudaFuncSetAttribute(step_kernel, cudaFuncAttributeMaxDynamicSharedMemorySize, SM_DYN);
        attr_done = true;
    }

    void *p_h1, *p_h2, *p_th;
    cudaGetSymbolAddress(&p_h1, g_h1);
    cudaGetSymbolAddress(&p_h2, g_h2);
    cudaGetSymbolAddress(&p_th, g_theta);   // g_theta[0]

    size_t npk = (size_t)NT * NT * 32;
    cvt_E_pack<<<(unsigned)((npk + 255) / 256), 256>>>(A);

    mlp1_kernel<<<(H1n * 4 + 255) / 256, 256>>>(W1, b1, xs);
    matvec4<<<(H2n * 32 + 255) / 256, 256>>>(W2, b2, (const float*)p_h1, (float*)p_h2, H2n, H1n, 1);
    matvec4<<<((size_t)Ln * 32 + 255) / 256, 256>>>(W3, b3, (const float*)p_h2, (float*)p_th, Ln, H2n, 0);
    cvt_th0<<<(Ln * 4 + 255) / 256, 256>>>();

    for (int i = 0; i < Tt; i++)
        step_kernel<<<399, 256, SM_DYN>>>(i, xs, ts, Bm, out);

    root_final<<<1, 256>>>(ts, out);
}

// round 12
// speedup vs baseline: 1.0492x; 1.0492x over previous
#include <cuda_runtime.h>
#include <cuda_fp16.h>
#include <cstdint>

#define Ln    6368
#define Tt    128
#define H1n   2133
#define H2n   4250
#define NT    398          // 16-row tiles: 6368/16
#define TPW   50           // k-tiles per warp (warp 7 gets 48)
#define CgT   5            // fragment-tiles per TMA group (2560 B)
#define NGRP  10           // groups per warp
#define THS   6376         // padded theta smem stride (halves) -> conflict-free LDS

// dynamic smem layout (bytes)
#define SM_TH    0                    // fp16 theta 4*THS*2 = 51008 (slot 51200)
#define SM_EBUF  51200                // 8 warps * 2 stages * 2560 = 40960
#define SM_MBAR  (51200 + 40960)      // 16 mbarriers
#define SM_DYN   (SM_MBAR + 128)      // 92288

// ---------------- device state ----------------
__device__ __align__(16) uint4  g_Epk[(size_t)NT * NT * 32];   // E fragments, 81 MB
__device__ __align__(16) float  g_theta[2][Ln * 4];            // fp32 theta [j][b]
__device__ __align__(16) __half g_thh[2][4][Ln];               // fp16 theta [b][j]
__device__ __align__(16) float  g_h1[H1n * 4];
__device__ __align__(16) float  g_h2[H2n * 4];
__device__ __align__(16) float  g_xhat[Tt][4][16];

// ---------------- helpers ----------------
__device__ __forceinline__ uint32_t s2u(const void* p) {
    uint32_t a;
    asm("{ .reg .u64 t; cvta.to.shared.u64 t, %1; cvt.u32.u64 %0, t; }" : "=r"(a) : "l"(p));
    return a;
}
#define MBAR_INIT(a, n) asm volatile("mbarrier.init.shared.b64 [%0], %1;" :: "r"(a), "r"(n) : "memory")
#define MBAR_EXPECT(a, b) asm volatile("mbarrier.arrive.expect_tx.shared.b64 _, [%0], %1;" :: "r"(a), "r"(b) : "memory")
#define MBAR_WAIT(a, p) asm volatile( \
    "{\n\t.reg .pred P1;\nWL_%=:\n\t" \
    "mbarrier.try_wait.parity.acquire.cta.shared::cta.b64 P1, [%0], %1, 0x989680;\n\t" \
    "@P1 bra.uni WD_%=;\n\tbra.uni WL_%=;\nWD_%=:\n\t}" \
    :: "r"(a), "r"(p) : "memory")
#define BULK_CP_EL(dst, src, bytes, mb, pol) \
    asm volatile("cp.async.bulk.shared::cta.global.mbarrier::complete_tx::bytes.L2::cache_hint " \
                 "[%0], [%1], %2, [%3], %4;" \
                 :: "r"(dst), "l"(src), "r"(bytes), "r"(mb), "l"(pol) : "memory")
#define PDL_LAUNCH_DEPS() asm volatile("griddepcontrol.launch_dependents;" ::: "memory")
#define PDL_WAIT()        asm volatile("griddepcontrol.wait;" ::: "memory")

// ---------------- E conversion + fragment repack ----------------
__global__ void cvt_E_pack(const float* __restrict__ A) {
    size_t idx = (size_t)blockIdx.x * blockDim.x + threadIdx.x;
    if (idx >= (size_t)NT * NT * 32) return;
    int lane = (int)(idx & 31);
    size_t tIdx = idx >> 5;
    int rt = (int)(tIdx / NT), jt = (int)(tIdx % NT);
    int r0 = rt * 16 + (lane >> 2);
    int c0 = jt * 16 + (lane & 3) * 2;
    const float* Ar0 = A + (size_t)r0 * Ln;
    const float* Ar8 = A + (size_t)(r0 + 8) * Ln;
    float2 p00 = *reinterpret_cast<const float2*>(Ar0 + c0);
    float2 p10 = *reinterpret_cast<const float2*>(Ar8 + c0);
    float2 p01 = *reinterpret_cast<const float2*>(Ar0 + c0 + 8);
    float2 p11 = *reinterpret_cast<const float2*>(Ar8 + c0 + 8);
    if (r0 == c0)         p00.x -= 0.999f;
    if (r0 == c0 + 1)     p00.y -= 0.999f;
    if (r0 + 8 == c0)     p10.x -= 0.999f;
    if (r0 + 8 == c0 + 1) p10.y -= 0.999f;
    if (r0 == c0 + 8)     p01.x -= 0.999f;
    if (r0 == c0 + 9)     p01.y -= 0.999f;
    if (r0 + 8 == c0 + 8) p11.x -= 0.999f;
    if (r0 + 8 == c0 + 9) p11.y -= 0.999f;
    __half2 h0 = __floats2half2_rn(p00.x, p00.y);
    __half2 h1 = __floats2half2_rn(p10.x, p10.y);
    __half2 h2 = __floats2half2_rn(p01.x, p01.y);
    __half2 h3 = __floats2half2_rn(p11.x, p11.y);
    uint4 v;
    v.x = *reinterpret_cast<unsigned*>(&h0);
    v.y = *reinterpret_cast<unsigned*>(&h1);
    v.z = *reinterpret_cast<unsigned*>(&h2);
    v.w = *reinterpret_cast<unsigned*>(&h3);
    g_Epk[idx] = v;
}

// ---------------- init MLP ----------------
__global__ void mlp1_kernel(const float* __restrict__ W1, const float* __restrict__ b1,
                            const float* __restrict__ xs) {
    int t = blockIdx.x * blockDim.x + threadIdx.x;
    if (t >= H1n * 4) return;
    int row = t >> 2, b = t & 3;
    float a = b1[row];
    const float* x0 = xs + (size_t)b * Tt * 16;
#pragma unroll
    for (int d = 0; d < 16; d++) a = fmaf(W1[row * 16 + d], x0[d], a);
    g_h1[row * 4 + b] = fmaxf(a, 0.0f);
}

__global__ void matvec4(const float* __restrict__ W, const float* __restrict__ bias,
                        const float* __restrict__ xin, float* __restrict__ yout,
                        int rows, int K, int relu) {
    int w = (blockIdx.x * blockDim.x + threadIdx.x) >> 5;
    int lane = threadIdx.x & 31;
    if (w >= rows) return;
    const float* Wr = W + (size_t)w * K;
    float a0 = 0.f, a1 = 0.f, a2 = 0.f, a3 = 0.f;
#pragma unroll 4
    for (int j = lane; j < K; j += 32) {
        float wv = Wr[j];
        float4 xv = reinterpret_cast<const float4*>(xin)[j];
        a0 = fmaf(wv, xv.x, a0); a1 = fmaf(wv, xv.y, a1);
        a2 = fmaf(wv, xv.z, a2); a3 = fmaf(wv, xv.w, a3);
    }
#pragma unroll
    for (int m = 16; m > 0; m >>= 1) {
        a0 += __shfl_xor_sync(0xffffffffu, a0, m);
        a1 += __shfl_xor_sync(0xffffffffu, a1, m);
        a2 += __shfl_xor_sync(0xffffffffu, a2, m);
        a3 += __shfl_xor_sync(0xffffffffu, a3, m);
    }
    if (lane == 0) {
        float bb = bias[w];
        a0 += bb; a1 += bb; a2 += bb; a3 += bb;
        if (relu) {
            a0 = fmaxf(a0, 0.f); a1 = fmaxf(a1, 0.f);
            a2 = fmaxf(a2, 0.f); a3 = fmaxf(a3, 0.f);
        }
        reinterpret_cast<float4*>(yout)[w] = make_float4(a0, a1, a2, a3);
    }
}

__global__ void cvt_th0() {
    int t = blockIdx.x * blockDim.x + threadIdx.x;
    if (t >= Ln * 4) return;
    int row = t >> 2, b = t & 3;
    g_thh[0][b][row] = __float2half(g_theta[0][row * 4 + b]);
}

// ---------------- tiny root MLP ----------------
__device__ void root_apply(int j, const float* __restrict__ th,
                           const float* __restrict__ ts, float* __restrict__ out) {
    __shared__ float rh0[4][64];
    __shared__ float rh1[4][64];
    int tid = threadIdx.x;
    int b = tid >> 6, k = tid & 63;
    float tj  = ts[b * Tt + j];
    float tin = (j == 0) ? tj : (2.0f * tj - ts[b * Tt + j - 1]);
    float h = fmaf(th[k * 4 + b], tin, th[(64 + k) * 4 + b]);
    rh0[b][k] = fmaxf(h, 0.0f);
    __syncthreads();
    float a = th[(4224 + k) * 4 + b];
#pragma unroll 8
    for (int c = 0; c < 64; c++)
        a = fmaf(th[(128 + k * 64 + c) * 4 + b], rh0[b][c], a);
    rh1[b][k] = fmaxf(a, 0.0f);
    __syncthreads();
    if (k < 32) {
        float o = th[(6336 + k) * 4 + b];
#pragma unroll 8
        for (int c = 0; c < 64; c++)
            o = fmaf(th[(4288 + k * 64 + c) * 4 + b], rh1[b][c], o);
        float v;
        if (k < 16) {
            v = tanhf(o);
            g_xhat[j][b][k] = v;
        } else {
            v = fmaxf(o, 0.0f) + log1pf(expf(-fabsf(o)));
        }
        out[((size_t)b * Tt + j) * 32 + k] = v;
    }
}

// ---------------- per-step kernel (R9 inner structure + PDL overlap) ----------------
// Preamble (mbar init + E TMA prefetch) runs BEFORE griddepcontrol.wait:
// E is static, so it legally overlaps the predecessor step's tail.
__global__ void __launch_bounds__(256, 2) step_kernel(int i, const float* __restrict__ xs,
                                                      const float* __restrict__ ts,
                                                      const float* __restrict__ Bm,
                                                      float* __restrict__ out) {
    if (blockIdx.x == 0) {
        if (threadIdx.x == 0) PDL_LAUNCH_DEPS();
        PDL_WAIT();                                // theta_i must be complete
        if (i >= 1) root_apply(i - 1, g_theta[i & 1], ts, out);
        return;
    }
    extern __shared__ __align__(1024) char dsm[];
    __half* th_s = reinterpret_cast<__half*>(dsm);
    uint32_t smem_base = s2u(dsm);
    uint32_t mbar_base = smem_base + SM_MBAR;

    __shared__ float sacc[8][16][8];
    __shared__ float sdiff[17 * 4];

    int tid = threadIdx.x, lane = tid & 31, w = tid >> 5;
    int rt = blockIdx.x - 1;
    int jt0 = w * TPW;
    int jtN = min(TPW, NT - jt0);                 // 50 (warp 7: 48)
    int ngroups = NGRP;

    uint32_t mybar = mbar_base + w * 16;
    uint32_t mybuf = smem_base + SM_EBUF + w * (2 * CgT * 512);
    const char* esrc = reinterpret_cast<const char*>(g_Epk) + ((size_t)rt * NT + jt0) * 512;

    uint64_t pol;
    asm("createpolicy.fractional.L2::evict_last.b64 %0, 1.0;" : "=l"(pol));

    // ---- pre-wait preamble: mbar init + E prefetch (independent of theta) ----
    if (tid < 16) MBAR_INIT(mbar_base + tid * 8, 1);
    __syncthreads();
    if (tid == 0) asm volatile("fence.proxy.async.shared::cta;" ::: "memory");
    __syncthreads();

#define ISSUE(g) do { \
        int _g = (g); \
        if (_g < ngroups && lane == 0) { \
            int _t0 = _g * CgT; \
            unsigned _bytes = (unsigned)(min(CgT, jtN - _t0) * 512); \
            uint32_t _mb = mybar + (_g & 1) * 8; \
            uint32_t _db = mybuf + (_g & 1) * (CgT * 512); \
            MBAR_EXPECT(_mb, _bytes); \
            BULK_CP_EL(_db, esrc + (size_t)_t0 * 512, _bytes, _mb, pol); \
        } \
    } while (0)

    ISSUE(0);
    ISSUE(1);
    if (tid == 0) PDL_LAUNCH_DEPS();

    // ---- wait for predecessor step to fully complete (theta/xhat visible) ----
    PDL_WAIT();

    const float* thin = g_theta[i & 1];

    // stage fp16 theta into padded smem (conflict-free stride)
    {
        const uint4* src = reinterpret_cast<const uint4*>(&g_thh[i & 1][0][0]);
        for (int k = tid; k < 4 * (Ln / 8); k += 256) {
            int b = k / (Ln / 8), q = k - b * (Ln / 8);
            *reinterpret_cast<uint4*>(th_s + b * THS + q * 8) = src[k];
        }
    }
    if (tid < 68) {
        int c = tid >> 2, b = tid & 3;
        float d;
        if (c == 0) {
            d = (i == 0) ? 0.0f : ts[b * Tt + i] - ts[b * Tt + i - 1];
        } else {
            float xt = xs[((size_t)b * Tt + i) * 16 + (c - 1)];
            float xp = (i < 2) ? xs[(size_t)b * Tt * 16 + (c - 1)]
                               : g_xhat[i - 2][b][c - 1];
            d = xt - xp;
        }
        sdiff[c * 4 + b] = d;
    }
    __syncthreads();

    int n = lane >> 2, k0 = (lane & 3) * 2;
    const __half* bn = th_s + n * THS;
    bool bvalid = (n < 4);

    float c0 = 0.f, c1 = 0.f, c2 = 0.f, c3 = 0.f;
    for (int g = 0; g < ngroups; g++) {
        int t0 = g * CgT;
        int nt = min(CgT, jtN - t0);
        // prefetch B fragments (smem theta, independent of TMA) before the wait
        unsigned pb0[CgT], pb1[CgT];
#pragma unroll
        for (int t = 0; t < CgT; t++) {
            pb0[t] = 0u; pb1[t] = 0u;
            if (bvalid && t < nt) {
                int jj = (jt0 + t0 + t) * 16 + k0;
                pb0[t] = *reinterpret_cast<const unsigned*>(bn + jj);
                pb1[t] = *reinterpret_cast<const unsigned*>(bn + jj + 8);
            }
        }
        MBAR_WAIT(mybar + (g & 1) * 8, (g >> 1) & 1);
        uint32_t bufb = mybuf + (g & 1) * (CgT * 512) + lane * 16;
#pragma unroll
        for (int t = 0; t < CgT; t++) {
            if (t >= nt) break;
            uint4 af;
            asm volatile("ld.shared.v4.u32 {%0,%1,%2,%3}, [%4];"
                         : "=r"(af.x), "=r"(af.y), "=r"(af.z), "=r"(af.w)
                         : "r"(bufb + t * 512));
            asm volatile(
                "mma.sync.aligned.m16n8k16.row.col.f32.f16.f16.f32 "
                "{%0,%1,%2,%3}, {%4,%5,%6,%7}, {%8,%9}, {%0,%1,%2,%3};"
                : "+f"(c0), "+f"(c1), "+f"(c2), "+f"(c3)
                : "r"(af.x), "r"(af.y), "r"(af.z), "r"(af.w), "r"(pb0[t]), "r"(pb1[t]));
        }
        __syncwarp();
        if (lane == 0) asm volatile("fence.proxy.async.shared::cta;" ::: "memory");
        ISSUE(g + 2);
    }
#undef ISSUE

    {
        int r = lane >> 2, cc = (lane & 3) * 2;
        sacc[w][r][cc]         = c0;
        sacc[w][r][cc + 1]     = c1;
        sacc[w][r + 8][cc]     = c2;
        sacc[w][r + 8][cc + 1] = c3;
    }
    __syncthreads();

    if (tid < 64) {
        int rr = tid >> 2, b = tid & 3;
        float v = 0.f;
#pragma unroll
        for (int kw = 0; kw < 8; kw++) v += sacc[kw][rr][b];
        int row = rt * 16 + rr;
        float y = fmaf(0.999f, thin[row * 4 + b], v);
        const float* bmr = Bm + (size_t)row * 17;
#pragma unroll
        for (int c = 0; c < 17; c++) y = fmaf(bmr[c], sdiff[c * 4 + b], y);
        g_theta[(i + 1) & 1][row * 4 + b] = y;
        g_thh[(i + 1) & 1][b][row] = __float2half(y);
    }
}

// ---------------- final root for step T-1 ----------------
__global__ void root_final(const float* __restrict__ ts, float* __restrict__ out) {
    PDL_WAIT();
    root_apply(Tt - 1, g_theta[Tt & 1], ts, out);
}

// ---------------- launch ----------------
extern "C" void kernel_launch(void* const* d_in, const int* in_sizes, int n_in,
                              void* d_out, int out_size) {
    const float* xs = (const float*)d_in[0];
    const float* ts = (const float*)d_in[1];
    const float* A  = (const float*)d_in[2];
    const float* Bm = (const float*)d_in[3];
    const float* W1 = (const float*)d_in[4];
    const float* b1 = (const float*)d_in[5];
    const float* W2 = (const float*)d_in[6];
    const float* b2 = (const float*)d_in[7];
    const float* W3 = (const float*)d_in[8];
    const float* b3 = (const float*)d_in[9];
    // d_in[10] = seed: dead (FORCING_PROB == 1.0)
    float* out = (float*)d_out;

    static bool attr_done = false;
    if (!attr_done) {
        cudaFuncSetAttribute(step_kernel, cudaFuncAttributeMaxDynamicSharedMemorySize, SM_DYN);
        attr_done = true;
    }

    void *p_h1, *p_h2, *p_th;
    cudaGetSymbolAddress(&p_h1, g_h1);
    cudaGetSymbolAddress(&p_h2, g_h2);
    cudaGetSymbolAddress(&p_th, g_theta);   // g_theta[0]

    size_t npk = (size_t)NT * NT * 32;
    cvt_E_pack<<<(unsigned)((npk + 255) / 256), 256>>>(A);

    mlp1_kernel<<<(H1n * 4 + 255) / 256, 256>>>(W1, b1, xs);
    matvec4<<<(H2n * 32 + 255) / 256, 256>>>(W2, b2, (const float*)p_h1, (float*)p_h2, H2n, H1n, 1);
    matvec4<<<((size_t)Ln * 32 + 255) / 256, 256>>>(W3, b3, (const float*)p_h2, (float*)p_th, Ln, H2n, 0);
    cvt_th0<<<(Ln * 4 + 255) / 256, 256>>>();

    // PDL-chained step kernels: preamble of step i+1 overlaps tail of step i
    cudaLaunchAttribute at[1];
    at[0].id = cudaLaunchAttributeProgrammaticStreamSerialization;
    at[0].val.programmaticStreamSerializationAllowed = 1;

    cudaLaunchConfig_t cfg = {};
    cfg.gridDim = dim3(399);
    cfg.blockDim = dim3(256);
    cfg.dynamicSmemBytes = SM_DYN;
    cfg.stream = 0;
    cfg.attrs = at;
    cfg.numAttrs = 1;

    for (int i = 0; i < Tt; i++)
        cudaLaunchKernelEx(&cfg, step_kernel, i, xs, ts, Bm, out);

    cudaLaunchConfig_t cfgr = {};
    cfgr.gridDim = dim3(1);
    cfgr.blockDim = dim3(256);
    cfgr.dynamicSmemBytes = 0;
    cfgr.stream = 0;
    cfgr.attrs = at;
    cfgr.numAttrs = 1;
    cudaLaunchKernelEx(&cfgr, root_final, ts, out);
}

// round 13
// speedup vs baseline: 1.0614x; 1.0116x over previous
#include <cuda_runtime.h>
#include <cuda_fp16.h>
#include <cstdint>

#define Ln    6368
#define Tt    128
#define H1n   2133
#define H2n   4250
#define NT    398          // 16-row tiles: 6368/16
#define TPW   50           // k-tiles per warp (warp 7 gets 48)
#define CgT   5            // fragment-tiles per TMA group (2560 B)
#define NGRP  10           // groups per warp
#define THS   6376         // padded theta smem stride (halves) -> conflict-free LDS

// dynamic smem layout (bytes)
#define SM_TH    0                    // fp16 theta 4*THS*2 = 51008 (slot 51200)
#define SM_EBUF  51200                // 8 warps * 2 stages * 2560 = 40960
#define SM_MBAR  (51200 + 40960)      // 16 E mbars + 1 theta mbar
#define SM_DYN   (SM_MBAR + 192)      // 92352

// ---------------- device state ----------------
__device__ __align__(16) uint4  g_Epk[(size_t)NT * NT * 32];   // E fragments, 81 MB
__device__ __align__(16) float  g_theta[2][Ln * 4];            // fp32 theta [j][b]
__device__ __align__(16) __half g_thh[2][4][Ln];               // fp16 theta [b][j]
__device__ __align__(16) float  g_h1[H1n * 4];
__device__ __align__(16) float  g_h2[H2n * 4];
__device__ __align__(16) float  g_xhat[Tt][4][16];

// ---------------- helpers ----------------
__device__ __forceinline__ uint32_t s2u(const void* p) {
    uint32_t a;
    asm("{ .reg .u64 t; cvta.to.shared.u64 t, %1; cvt.u32.u64 %0, t; }" : "=r"(a) : "l"(p));
    return a;
}
#define MBAR_INIT(a, n) asm volatile("mbarrier.init.shared.b64 [%0], %1;" :: "r"(a), "r"(n) : "memory")
#define MBAR_EXPECT(a, b) asm volatile("mbarrier.arrive.expect_tx.shared.b64 _, [%0], %1;" :: "r"(a), "r"(b) : "memory")
#define MBAR_WAIT(a, p) asm volatile( \
    "{\n\t.reg .pred P1;\nWL_%=:\n\t" \
    "mbarrier.try_wait.parity.acquire.cta.shared::cta.b64 P1, [%0], %1, 0x989680;\n\t" \
    "@P1 bra.uni WD_%=;\n\tbra.uni WL_%=;\nWD_%=:\n\t}" \
    :: "r"(a), "r"(p) : "memory")
#define BULK_CP(dst, src, bytes, mb) \
    asm volatile("cp.async.bulk.shared::cta.global.mbarrier::complete_tx::bytes [%0], [%1], %2, [%3];" \
                 :: "r"(dst), "l"(src), "r"(bytes), "r"(mb) : "memory")
#define BULK_CP_EL(dst, src, bytes, mb, pol) \
    asm volatile("cp.async.bulk.shared::cta.global.mbarrier::complete_tx::bytes.L2::cache_hint " \
                 "[%0], [%1], %2, [%3], %4;" \
                 :: "r"(dst), "l"(src), "r"(bytes), "r"(mb), "l"(pol) : "memory")
#define PDL_LAUNCH_DEPS() asm volatile("griddepcontrol.launch_dependents;" ::: "memory")
#define PDL_WAIT()        asm volatile("griddepcontrol.wait;" ::: "memory")

// ---------------- E conversion + fragment repack (evict_last stores) ----------------
__global__ void cvt_E_pack(const float* __restrict__ A) {
    size_t idx = (size_t)blockIdx.x * blockDim.x + threadIdx.x;
    if (idx >= (size_t)NT * NT * 32) return;
    int lane = (int)(idx & 31);
    size_t tIdx = idx >> 5;
    int rt = (int)(tIdx / NT), jt = (int)(tIdx % NT);
    int r0 = rt * 16 + (lane >> 2);
    int c0 = jt * 16 + (lane & 3) * 2;
    const float* Ar0 = A + (size_t)r0 * Ln;
    const float* Ar8 = A + (size_t)(r0 + 8) * Ln;
    float2 p00 = *reinterpret_cast<const float2*>(Ar0 + c0);
    float2 p10 = *reinterpret_cast<const float2*>(Ar8 + c0);
    float2 p01 = *reinterpret_cast<const float2*>(Ar0 + c0 + 8);
    float2 p11 = *reinterpret_cast<const float2*>(Ar8 + c0 + 8);
    if (r0 == c0)         p00.x -= 0.999f;
    if (r0 == c0 + 1)     p00.y -= 0.999f;
    if (r0 + 8 == c0)     p10.x -= 0.999f;
    if (r0 + 8 == c0 + 1) p10.y -= 0.999f;
    if (r0 == c0 + 8)     p01.x -= 0.999f;
    if (r0 == c0 + 9)     p01.y -= 0.999f;
    if (r0 + 8 == c0 + 8) p11.x -= 0.999f;
    if (r0 + 8 == c0 + 9) p11.y -= 0.999f;
    __half2 h0 = __floats2half2_rn(p00.x, p00.y);
    __half2 h1 = __floats2half2_rn(p10.x, p10.y);
    __half2 h2 = __floats2half2_rn(p01.x, p01.y);
    __half2 h3 = __floats2half2_rn(p11.x, p11.y);
    uint64_t pol;
    asm("createpolicy.fractional.L2::evict_last.b64 %0, 1.0;" : "=l"(pol));
    asm volatile("st.global.L2::cache_hint.v4.b32 [%0], {%1,%2,%3,%4}, %5;"
                 :: "l"(&g_Epk[idx]),
                    "r"(*reinterpret_cast<unsigned*>(&h0)),
                    "r"(*reinterpret_cast<unsigned*>(&h1)),
                    "r"(*reinterpret_cast<unsigned*>(&h2)),
                    "r"(*reinterpret_cast<unsigned*>(&h3)),
                    "l"(pol) : "memory");
}

// ---------------- init MLP ----------------
__global__ void mlp1_kernel(const float* __restrict__ W1, const float* __restrict__ b1,
                            const float* __restrict__ xs) {
    int t = blockIdx.x * blockDim.x + threadIdx.x;
    if (t >= H1n * 4) return;
    int row = t >> 2, b = t & 3;
    float a = b1[row];
    const float* x0 = xs + (size_t)b * Tt * 16;
#pragma unroll
    for (int d = 0; d < 16; d++) a = fmaf(W1[row * 16 + d], x0[d], a);
    g_h1[row * 4 + b] = fmaxf(a, 0.0f);
}

__global__ void matvec4(const float* __restrict__ W, const float* __restrict__ bias,
                        const float* __restrict__ xin, float* __restrict__ yout,
                        int rows, int K, int relu) {
    int w = (blockIdx.x * blockDim.x + threadIdx.x) >> 5;
    int lane = threadIdx.x & 31;
    if (w >= rows) return;
    const float* Wr = W + (size_t)w * K;
    float a0 = 0.f, a1 = 0.f, a2 = 0.f, a3 = 0.f;
#pragma unroll 4
    for (int j = lane; j < K; j += 32) {
        float wv = Wr[j];
        float4 xv = reinterpret_cast<const float4*>(xin)[j];
        a0 = fmaf(wv, xv.x, a0); a1 = fmaf(wv, xv.y, a1);
        a2 = fmaf(wv, xv.z, a2); a3 = fmaf(wv, xv.w, a3);
    }
#pragma unroll
    for (int m = 16; m > 0; m >>= 1) {
        a0 += __shfl_xor_sync(0xffffffffu, a0, m);
        a1 += __shfl_xor_sync(0xffffffffu, a1, m);
        a2 += __shfl_xor_sync(0xffffffffu, a2, m);
        a3 += __shfl_xor_sync(0xffffffffu, a3, m);
    }
    if (lane == 0) {
        float bb = bias[w];
        a0 += bb; a1 += bb; a2 += bb; a3 += bb;
        if (relu) {
            a0 = fmaxf(a0, 0.f); a1 = fmaxf(a1, 0.f);
            a2 = fmaxf(a2, 0.f); a3 = fmaxf(a3, 0.f);
        }
        reinterpret_cast<float4*>(yout)[w] = make_float4(a0, a1, a2, a3);
    }
}

__global__ void cvt_th0() {
    int t = blockIdx.x * blockDim.x + threadIdx.x;
    if (t >= Ln * 4) return;
    int row = t >> 2, b = t & 3;
    g_thh[0][b][row] = __float2half(g_theta[0][row * 4 + b]);
}

// ---------------- tiny root MLP ----------------
__device__ void root_apply(int j, const float* __restrict__ th,
                           const float* __restrict__ ts, float* __restrict__ out) {
    __shared__ float rh0[4][64];
    __shared__ float rh1[4][64];
    int tid = threadIdx.x;
    int b = tid >> 6, k = tid & 63;
    float tj  = ts[b * Tt + j];
    float tin = (j == 0) ? tj : (2.0f * tj - ts[b * Tt + j - 1]);
    float h = fmaf(th[k * 4 + b], tin, th[(64 + k) * 4 + b]);
    rh0[b][k] = fmaxf(h, 0.0f);
    __syncthreads();
    float a = th[(4224 + k) * 4 + b];
#pragma unroll 8
    for (int c = 0; c < 64; c++)
        a = fmaf(th[(128 + k * 64 + c) * 4 + b], rh0[b][c], a);
    rh1[b][k] = fmaxf(a, 0.0f);
    __syncthreads();
    if (k < 32) {
        float o = th[(6336 + k) * 4 + b];
#pragma unroll 8
        for (int c = 0; c < 64; c++)
            o = fmaf(th[(4288 + k * 64 + c) * 4 + b], rh1[b][c], o);
        float v;
        if (k < 16) {
            v = tanhf(o);
            g_xhat[j][b][k] = v;
        } else {
            v = fmaxf(o, 0.0f) + log1pf(expf(-fabsf(o)));
        }
        out[((size_t)b * Tt + j) * 32 + k] = v;
    }
}

// ---------------- per-step kernel (PDL + TMA theta + evict_last E) ----------------
__global__ void __launch_bounds__(256, 2) step_kernel(int i, const float* __restrict__ xs,
                                                      const float* __restrict__ ts,
                                                      const float* __restrict__ Bm,
                                                      float* __restrict__ out) {
    if (blockIdx.x == 0) {
        if (threadIdx.x == 0) PDL_LAUNCH_DEPS();
        PDL_WAIT();
        if (i >= 1) root_apply(i - 1, g_theta[i & 1], ts, out);
        return;
    }
    extern __shared__ __align__(1024) char dsm[];
    __half* th_s = reinterpret_cast<__half*>(dsm);
    uint32_t smem_base = s2u(dsm);
    uint32_t mbar_base = smem_base + SM_MBAR;
    uint32_t tbar = mbar_base + 16 * 8;

    __shared__ float sacc[8][16][8];
    __shared__ float sdiff[17 * 4];

    int tid = threadIdx.x, lane = tid & 31, w = tid >> 5;
    int rt = blockIdx.x - 1;
    int jt0 = w * TPW;
    int jtN = min(TPW, NT - jt0);                 // 50 (warp 7: 48)
    int ngroups = NGRP;

    uint32_t mybar = mbar_base + w * 16;
    uint32_t mybuf = smem_base + SM_EBUF + w * (2 * CgT * 512);
    const char* esrc = reinterpret_cast<const char*>(g_Epk) + ((size_t)rt * NT + jt0) * 512;

    uint64_t pol;
    asm("createpolicy.fractional.L2::evict_last.b64 %0, 1.0;" : "=l"(pol));

    // ---- pre-wait preamble: mbar init + E prefetch (independent of theta) ----
    if (tid < 17) MBAR_INIT(mbar_base + tid * 8, 1);
    __syncthreads();
    if (tid == 0) asm volatile("fence.proxy.async.shared::cta;" ::: "memory");
    __syncthreads();

#define ISSUE(g) do { \
        int _g = (g); \
        if (_g < ngroups && lane == 0) { \
            int _t0 = _g * CgT; \
            unsigned _bytes = (unsigned)(min(CgT, jtN - _t0) * 512); \
            uint32_t _mb = mybar + (_g & 1) * 8; \
            uint32_t _db = mybuf + (_g & 1) * (CgT * 512); \
            MBAR_EXPECT(_mb, _bytes); \
            BULK_CP_EL(_db, esrc + (size_t)_t0 * 512, _bytes, _mb, pol); \
        } \
    } while (0)

    ISSUE(0);
    ISSUE(1);
    if (tid == 0) PDL_LAUNCH_DEPS();

    // ---- wait for predecessor step to fully complete (theta/xhat visible) ----
    PDL_WAIT();

    const float* thin = g_theta[i & 1];

    // stage fp16 theta via 4 bulk copies into the padded smem stride
    if (tid == 0) {
        MBAR_EXPECT(tbar, 4 * Ln * 2);
#pragma unroll
        for (int b = 0; b < 4; b++)
            BULK_CP(smem_base + SM_TH + b * (THS * 2),
                    reinterpret_cast<const char*>(&g_thh[i & 1][b][0]), Ln * 2, tbar);
    }
    if (tid < 68) {
        int c = tid >> 2, b = tid & 3;
        float d;
        if (c == 0) {
            d = (i == 0) ? 0.0f : ts[b * Tt + i] - ts[b * Tt + i - 1];
        } else {
            float xt = xs[((size_t)b * Tt + i) * 16 + (c - 1)];
            float xp = (i < 2) ? xs[(size_t)b * Tt * 16 + (c - 1)]
                               : g_xhat[i - 2][b][c - 1];
            d = xt - xp;
        }
        sdiff[c * 4 + b] = d;
    }
    __syncthreads();

    int n = lane >> 2, k0 = (lane & 3) * 2;
    const __half* bn = th_s + n * THS;
    bool bvalid = (n < 4);

    MBAR_WAIT(tbar, 0);   // theta resident in smem

    float c0 = 0.f, c1 = 0.f, c2 = 0.f, c3 = 0.f;
    for (int g = 0; g < ngroups; g++) {
        int t0 = g * CgT;
        int nt = min(CgT, jtN - t0);
        // prefetch B fragments (smem theta, independent of E TMA) before the wait
        unsigned pb0[CgT], pb1[CgT];
#pragma unroll
        for (int t = 0; t < CgT; t++) {
            pb0[t] = 0u; pb1[t] = 0u;
            if (bvalid && t < nt) {
                int jj = (jt0 + t0 + t) * 16 + k0;
                pb0[t] = *reinterpret_cast<const unsigned*>(bn + jj);
                pb1[t] = *reinterpret_cast<const unsigned*>(bn + jj + 8);
            }
        }
        MBAR_WAIT(mybar + (g & 1) * 8, (g >> 1) & 1);
        uint32_t bufb = mybuf + (g & 1) * (CgT * 512) + lane * 16;
#pragma unroll
        for (int t = 0; t < CgT; t++) {
            if (t >= nt) break;
            uint4 af;
            asm volatile("ld.shared.v4.u32 {%0,%1,%2,%3}, [%4];"
                         : "=r"(af.x), "=r"(af.y), "=r"(af.z), "=r"(af.w)
                         : "r"(bufb + t * 512));
            asm volatile(
                "mma.sync.aligned.m16n8k16.row.col.f32.f16.f16.f32 "
                "{%0,%1,%2,%3}, {%4,%5,%6,%7}, {%8,%9}, {%0,%1,%2,%3};"
                : "+f"(c0), "+f"(c1), "+f"(c2), "+f"(c3)
                : "r"(af.x), "r"(af.y), "r"(af.z), "r"(af.w), "r"(pb0[t]), "r"(pb1[t]));
        }
        __syncwarp();
        if (lane == 0) asm volatile("fence.proxy.async.shared::cta;" ::: "memory");
        ISSUE(g + 2);
    }
#undef ISSUE

    {
        int r = lane >> 2, cc = (lane & 3) * 2;
        sacc[w][r][cc]         = c0;
        sacc[w][r][cc + 1]     = c1;
        sacc[w][r + 8][cc]     = c2;
        sacc[w][r + 8][cc + 1] = c3;
    }
    __syncthreads();

    if (tid < 64) {
        int rr = tid >> 2, b = tid & 3;
        float v = 0.f;
#pragma unroll
        for (int kw = 0; kw < 8; kw++) v += sacc[kw][rr][b];
        int row = rt * 16 + rr;
        float y = fmaf(0.999f, thin[row * 4 + b], v);
        const float* bmr = Bm + (size_t)row * 17;
#pragma unroll
        for (int c = 0; c < 17; c++) y = fmaf(bmr[c], sdiff[c * 4 + b], y);
        g_theta[(i + 1) & 1][row * 4 + b] = y;
        g_thh[(i + 1) & 1][b][row] = __float2half(y);
    }
}

// ---------------- final root for step T-1 ----------------
__global__ void root_final(const float* __restrict__ ts, float* __restrict__ out) {
    PDL_WAIT();
    root_apply(Tt - 1, g_theta[Tt & 1], ts, out);
}

// ---------------- launch ----------------
extern "C" void kernel_launch(void* const* d_in, const int* in_sizes, int n_in,
                              void* d_out, int out_size) {
    const float* xs = (const float*)d_in[0];
    const float* ts = (const float*)d_in[1];
    const float* A  = (const float*)d_in[2];
    const float* Bm = (const float*)d_in[3];
    const float* W1 = (const float*)d_in[4];
    const float* b1 = (const float*)d_in[5];
    const float* W2 = (const float*)d_in[6];
    const float* b2 = (const float*)d_in[7];
    const float* W3 = (const float*)d_in[8];
    const float* b3 = (const float*)d_in[9];
    // d_in[10] = seed: dead (FORCING_PROB == 1.0)
    float* out = (float*)d_out;

    static bool attr_done = false;
    if (!attr_done) {
        cudaFuncSetAttribute(step_kernel, cudaFuncAttributeMaxDynamicSharedMemorySize, SM_DYN);
        attr_done = true;
    }

    void *p_h1, *p_h2, *p_th;
    cudaGetSymbolAddress(&p_h1, g_h1);
    cudaGetSymbolAddress(&p_h2, g_h2);
    cudaGetSymbolAddress(&p_th, g_theta);   // g_theta[0]

    size_t npk = (size_t)NT * NT * 32;
    cvt_E_pack<<<(unsigned)((npk + 255) / 256), 256>>>(A);

    mlp1_kernel<<<(H1n * 4 + 255) / 256, 256>>>(W1, b1, xs);
    matvec4<<<(H2n * 32 + 255) / 256, 256>>>(W2, b2, (const float*)p_h1, (float*)p_h2, H2n, H1n, 1);
    matvec4<<<((size_t)Ln * 32 + 255) / 256, 256>>>(W3, b3, (const float*)p_h2, (float*)p_th, Ln, H2n, 0);
    cvt_th0<<<(Ln * 4 + 255) / 256, 256>>>();

    // PDL-chained step kernels: preamble of step i+1 overlaps tail of step i
    cudaLaunchAttribute at[1];
    at[0].id = cudaLaunchAttributeProgrammaticStreamSerialization;
    at[0].val.programmaticStreamSerializationAllowed = 1;

    cudaLaunchConfig_t cfg = {};
    cfg.gridDim = dim3(399);
    cfg.blockDim = dim3(256);
    cfg.dynamicSmemBytes = SM_DYN;
    cfg.stream = 0;
    cfg.attrs = at;
    cfg.numAttrs = 1;

    for (int i = 0; i < Tt; i++)
        cudaLaunchKernelEx(&cfg, step_kernel, i, xs, ts, Bm, out);

    cudaLaunchConfig_t cfgr = {};
    cfgr.gridDim = dim3(1);
    cfgr.blockDim = dim3(256);
    cfgr.dynamicSmemBytes = 0;
    cfgr.stream = 0;
    cfgr.attrs = at;
    cfgr.numAttrs = 1;
    cudaLaunchKernelEx(&cfgr, root_final, ts, out);
}

// round 14
// speedup vs baseline: 1.0664x; 1.0047x over previous
#include <cuda_runtime.h>
#include <cuda_fp16.h>
#include <cstdint>

#define Ln    6368
#define Tt    128
#define H1n   2133
#define H2n   4250
#define NT    398          // 16-row tiles: 6368/16
#define TPW   50           // k-tiles per warp (warp 7 gets 48)
#define CgT   5            // fragment-tiles per TMA group (2560 B)
#define NGRP  10           // groups per warp
#define NST   3            // ring stages
#define THS   6376         // padded theta smem stride (halves) -> conflict-free LDS

// dynamic smem layout (bytes)
#define SM_TH    0                         // fp16 theta 4*THS*2 = 51008 (slot 51200)
#define SM_EBUF  51200                     // 8 warps * 3 stages * 2560 = 61440
#define SM_MBAR  (51200 + 61440)           // 24 E mbars + 1 theta mbar (256)
#define SM_SDIFF (SM_MBAR + 256)           // 272 (pad 288)
#define SM_DYN   (SM_SDIFF + 288)          // 113184
// sacc (4KB) aliases SM_EBUF after the mainloop; root scratch aliases SM_EBUF in block 0.

// ---------------- device state ----------------
__device__ __align__(16) uint4  g_Epk[(size_t)NT * NT * 32];   // E fragments, 81 MB
__device__ __align__(16) float  g_theta[2][Ln * 4];            // fp32 theta [j][b]
__device__ __align__(16) __half g_thh[2][4][Ln];               // fp16 theta [b][j]
__device__ __align__(16) float  g_h1[H1n * 4];
__device__ __align__(16) float  g_h2[H2n * 4];
__device__ __align__(16) float  g_xhat[Tt][4][16];

// ---------------- helpers ----------------
__device__ __forceinline__ uint32_t s2u(const void* p) {
    uint32_t a;
    asm("{ .reg .u64 t; cvta.to.shared.u64 t, %1; cvt.u32.u64 %0, t; }" : "=r"(a) : "l"(p));
    return a;
}
#define MBAR_INIT(a, n) asm volatile("mbarrier.init.shared.b64 [%0], %1;" :: "r"(a), "r"(n) : "memory")
#define MBAR_EXPECT(a, b) asm volatile("mbarrier.arrive.expect_tx.shared.b64 _, [%0], %1;" :: "r"(a), "r"(b) : "memory")
#define MBAR_WAIT(a, p) asm volatile( \
    "{\n\t.reg .pred P1;\nWL_%=:\n\t" \
    "mbarrier.try_wait.parity.acquire.cta.shared::cta.b64 P1, [%0], %1, 0x989680;\n\t" \
    "@P1 bra.uni WD_%=;\n\tbra.uni WL_%=;\nWD_%=:\n\t}" \
    :: "r"(a), "r"(p) : "memory")
#define BULK_CP(dst, src, bytes, mb) \
    asm volatile("cp.async.bulk.shared::cta.global.mbarrier::complete_tx::bytes [%0], [%1], %2, [%3];" \
                 :: "r"(dst), "l"(src), "r"(bytes), "r"(mb) : "memory")
#define BULK_CP_EL(dst, src, bytes, mb, pol) \
    asm volatile("cp.async.bulk.shared::cta.global.mbarrier::complete_tx::bytes.L2::cache_hint " \
                 "[%0], [%1], %2, [%3], %4;" \
                 :: "r"(dst), "l"(src), "r"(bytes), "r"(mb), "l"(pol) : "memory")
#define PDL_LAUNCH_DEPS() asm volatile("griddepcontrol.launch_dependents;" ::: "memory")
#define PDL_WAIT()        asm volatile("griddepcontrol.wait;" ::: "memory")

// ---------------- E conversion + fragment repack (evict_last stores) ----------------
__global__ void cvt_E_pack(const float* __restrict__ A) {
    size_t idx = (size_t)blockIdx.x * blockDim.x + threadIdx.x;
    if (idx >= (size_t)NT * NT * 32) return;
    int lane = (int)(idx & 31);
    size_t tIdx = idx >> 5;
    int rt = (int)(tIdx / NT), jt = (int)(tIdx % NT);
    int r0 = rt * 16 + (lane >> 2);
    int c0 = jt * 16 + (lane & 3) * 2;
    const float* Ar0 = A + (size_t)r0 * Ln;
    const float* Ar8 = A + (size_t)(r0 + 8) * Ln;
    float2 p00 = *reinterpret_cast<const float2*>(Ar0 + c0);
    float2 p10 = *reinterpret_cast<const float2*>(Ar8 + c0);
    float2 p01 = *reinterpret_cast<const float2*>(Ar0 + c0 + 8);
    float2 p11 = *reinterpret_cast<const float2*>(Ar8 + c0 + 8);
    if (r0 == c0)         p00.x -= 0.999f;
    if (r0 == c0 + 1)     p00.y -= 0.999f;
    if (r0 + 8 == c0)     p10.x -= 0.999f;
    if (r0 + 8 == c0 + 1) p10.y -= 0.999f;
    if (r0 == c0 + 8)     p01.x -= 0.999f;
    if (r0 == c0 + 9)     p01.y -= 0.999f;
    if (r0 + 8 == c0 + 8) p11.x -= 0.999f;
    if (r0 + 8 == c0 + 9) p11.y -= 0.999f;
    __half2 h0 = __floats2half2_rn(p00.x, p00.y);
    __half2 h1 = __floats2half2_rn(p10.x, p10.y);
    __half2 h2 = __floats2half2_rn(p01.x, p01.y);
    __half2 h3 = __floats2half2_rn(p11.x, p11.y);
    uint64_t pol;
    asm("createpolicy.fractional.L2::evict_last.b64 %0, 1.0;" : "=l"(pol));
    asm volatile("st.global.L2::cache_hint.v4.b32 [%0], {%1,%2,%3,%4}, %5;"
                 :: "l"(&g_Epk[idx]),
                    "r"(*reinterpret_cast<unsigned*>(&h0)),
                    "r"(*reinterpret_cast<unsigned*>(&h1)),
                    "r"(*reinterpret_cast<unsigned*>(&h2)),
                    "r"(*reinterpret_cast<unsigned*>(&h3)),
                    "l"(pol) : "memory");
}

// ---------------- init MLP ----------------
__global__ void mlp1_kernel(const float* __restrict__ W1, const float* __restrict__ b1,
                            const float* __restrict__ xs) {
    int t = blockIdx.x * blockDim.x + threadIdx.x;
    if (t >= H1n * 4) return;
    int row = t >> 2, b = t & 3;
    float a = b1[row];
    const float* x0 = xs + (size_t)b * Tt * 16;
#pragma unroll
    for (int d = 0; d < 16; d++) a = fmaf(W1[row * 16 + d], x0[d], a);
    g_h1[row * 4 + b] = fmaxf(a, 0.0f);
}

// warp-per-row fp32 matvec; writeh!=0 also writes fp16-transposed output to g_thh[0]
__global__ void matvec4(const float* __restrict__ W, const float* __restrict__ bias,
                        const float* __restrict__ xin, float* __restrict__ yout,
                        int rows, int K, int relu, int writeh) {
    int w = (blockIdx.x * blockDim.x + threadIdx.x) >> 5;
    int lane = threadIdx.x & 31;
    if (w >= rows) return;
    const float* Wr = W + (size_t)w * K;
    float a0 = 0.f, a1 = 0.f, a2 = 0.f, a3 = 0.f;
#pragma unroll 4
    for (int j = lane; j < K; j += 32) {
        float wv = Wr[j];
        float4 xv = reinterpret_cast<const float4*>(xin)[j];
        a0 = fmaf(wv, xv.x, a0); a1 = fmaf(wv, xv.y, a1);
        a2 = fmaf(wv, xv.z, a2); a3 = fmaf(wv, xv.w, a3);
    }
#pragma unroll
    for (int m = 16; m > 0; m >>= 1) {
        a0 += __shfl_xor_sync(0xffffffffu, a0, m);
        a1 += __shfl_xor_sync(0xffffffffu, a1, m);
        a2 += __shfl_xor_sync(0xffffffffu, a2, m);
        a3 += __shfl_xor_sync(0xffffffffu, a3, m);
    }
    if (lane == 0) {
        float bb = bias[w];
        a0 += bb; a1 += bb; a2 += bb; a3 += bb;
        if (relu) {
            a0 = fmaxf(a0, 0.f); a1 = fmaxf(a1, 0.f);
            a2 = fmaxf(a2, 0.f); a3 = fmaxf(a3, 0.f);
        }
        reinterpret_cast<float4*>(yout)[w] = make_float4(a0, a1, a2, a3);
        if (writeh) {
            g_thh[0][0][w] = __float2half(a0);
            g_thh[0][1][w] = __float2half(a1);
            g_thh[0][2][w] = __float2half(a2);
            g_thh[0][3][w] = __float2half(a3);
        }
    }
}

// ---------------- tiny root MLP (scratch supplied by caller) ----------------
__device__ void root_apply(int j, const float* __restrict__ th,
                           const float* __restrict__ ts, float* __restrict__ out,
                           float* rh0, float* rh1) {          // each [4][64]
    int tid = threadIdx.x;
    int b = tid >> 6, k = tid & 63;
    float tj  = ts[b * Tt + j];
    float tin = (j == 0) ? tj : (2.0f * tj - ts[b * Tt + j - 1]);
    float h = fmaf(th[k * 4 + b], tin, th[(64 + k) * 4 + b]);
    rh0[b * 64 + k] = fmaxf(h, 0.0f);
    __syncthreads();
    float a = th[(4224 + k) * 4 + b];
#pragma unroll 8
    for (int c = 0; c < 64; c++)
        a = fmaf(th[(128 + k * 64 + c) * 4 + b], rh0[b * 64 + c], a);
    rh1[b * 64 + k] = fmaxf(a, 0.0f);
    __syncthreads();
    if (k < 32) {
        float o = th[(6336 + k) * 4 + b];
#pragma unroll 8
        for (int c = 0; c < 64; c++)
            o = fmaf(th[(4288 + k * 64 + c) * 4 + b], rh1[b * 64 + c], o);
        float v;
        if (k < 16) {
            v = tanhf(o);
            g_xhat[j][b][k] = v;
        } else {
            v = fmaxf(o, 0.0f) + log1pf(expf(-fabsf(o)));
        }
        out[((size_t)b * Tt + j) * 32 + k] = v;
    }
}

// ---------------- per-step kernel (PDL + 3-stage E ring + TMA theta) ----------------
__global__ void __launch_bounds__(256, 2) step_kernel(int i, const float* __restrict__ xs,
                                                      const float* __restrict__ ts,
                                                      const float* __restrict__ Bm,
                                                      float* __restrict__ out) {
    extern __shared__ __align__(1024) char dsm[];
    if (blockIdx.x == 0) {
        if (threadIdx.x == 0) PDL_LAUNCH_DEPS();
        PDL_WAIT();
        if (i >= 1)
            root_apply(i - 1, g_theta[i & 1], ts, out,
                       reinterpret_cast<float*>(dsm + SM_EBUF),
                       reinterpret_cast<float*>(dsm + SM_EBUF + 1024));
        return;
    }
    __half* th_s = reinterpret_cast<__half*>(dsm);
    float* sdiff = reinterpret_cast<float*>(dsm + SM_SDIFF);    // [17][4]
    float* sacc  = reinterpret_cast<float*>(dsm + SM_EBUF);     // [8][16][8], aliased post-loop
    uint32_t smem_base = s2u(dsm);
    uint32_t mbar_base = smem_base + SM_MBAR;
    uint32_t tbar = mbar_base + 24 * 8;

    int tid = threadIdx.x, lane = tid & 31, w = tid >> 5;
    int rt = blockIdx.x - 1;
    int jt0 = w * TPW;
    int jtN = min(TPW, NT - jt0);                 // 50 (warp 7: 48)
    int ngroups = NGRP;

    uint32_t mybar = mbar_base + w * (NST * 8);
    uint32_t mybuf = smem_base + SM_EBUF + w * (NST * CgT * 512);
    const char* esrc = reinterpret_cast<const char*>(g_Epk) + ((size_t)rt * NT + jt0) * 512;

    uint64_t pol;
    asm("createpolicy.fractional.L2::evict_last.b64 %0, 1.0;" : "=l"(pol));

    // ---- pre-wait preamble: mbar init + E prefetch (independent of theta) ----
    if (tid < 25) MBAR_INIT(mbar_base + tid * 8, 1);
    __syncthreads();
    if (tid == 0) asm volatile("fence.proxy.async.shared::cta;" ::: "memory");
    __syncthreads();

#define ISSUE(g) do { \
        int _g = (g); \
        if (_g < ngroups && lane == 0) { \
            int _t0 = _g * CgT; \
            unsigned _bytes = (unsigned)(min(CgT, jtN - _t0) * 512); \
            int _s = _g % NST; \
            MBAR_EXPECT(mybar + _s * 8, _bytes); \
            BULK_CP_EL(mybuf + _s * (CgT * 512), esrc + (size_t)_t0 * 512, _bytes, mybar + _s * 8, pol); \
        } \
    } while (0)

    ISSUE(0); ISSUE(1); ISSUE(2);
    if (tid == 0) PDL_LAUNCH_DEPS();

    // ---- wait for predecessor step (theta/xhat now visible) ----
    PDL_WAIT();

    const float* thin = g_theta[i & 1];

    // stage fp16 theta via 4 bulk copies into the padded smem stride
    if (tid == 0) {
        MBAR_EXPECT(tbar, 4 * Ln * 2);
#pragma unroll
        for (int b = 0; b < 4; b++)
            BULK_CP(smem_base + SM_TH + b * (THS * 2),
                    reinterpret_cast<const char*>(&g_thh[i & 1][b][0]), Ln * 2, tbar);
    }
    if (tid < 68) {
        int c = tid >> 2, b = tid & 3;
        float d;
        if (c == 0) {
            d = (i == 0) ? 0.0f : ts[b * Tt + i] - ts[b * Tt + i - 1];
        } else {
            float xt = xs[((size_t)b * Tt + i) * 16 + (c - 1)];
            float xp = (i < 2) ? xs[(size_t)b * Tt * 16 + (c - 1)]
                               : g_xhat[i - 2][b][c - 1];
            d = xt - xp;
        }
        sdiff[c * 4 + b] = d;
    }
    __syncthreads();

    int n = lane >> 2, k0 = (lane & 3) * 2;
    const __half* bn = th_s + n * THS;
    bool bvalid = (n < 4);

    MBAR_WAIT(tbar, 0);   // theta resident in smem

    float c0 = 0.f, c1 = 0.f, c2 = 0.f, c3 = 0.f;
    for (int g = 0; g < ngroups; g++) {
        int t0 = g * CgT;
        int nt = min(CgT, jtN - t0);
        // prefetch B fragments (smem theta, independent of E TMA) before the wait
        unsigned pb0[CgT], pb1[CgT];
#pragma unroll
        for (int t = 0; t < CgT; t++) {
            pb0[t] = 0u; pb1[t] = 0u;
            if (bvalid && t < nt) {
                int jj = (jt0 + t0 + t) * 16 + k0;
                pb0[t] = *reinterpret_cast<const unsigned*>(bn + jj);
                pb1[t] = *reinterpret_cast<const unsigned*>(bn + jj + 8);
            }
        }
        int s = g % NST, ph = (g / NST) & 1;
        MBAR_WAIT(mybar + s * 8, ph);
        uint32_t bufb = mybuf + s * (CgT * 512) + lane * 16;
#pragma unroll
        for (int t = 0; t < CgT; t++) {
            if (t >= nt) break;
            uint4 af;
            asm volatile("ld.shared.v4.u32 {%0,%1,%2,%3}, [%4];"
                         : "=r"(af.x), "=r"(af.y), "=r"(af.z), "=r"(af.w)
                         : "r"(bufb + t * 512));
            asm volatile(
                "mma.sync.aligned.m16n8k16.row.col.f32.f16.f16.f32 "
                "{%0,%1,%2,%3}, {%4,%5,%6,%7}, {%8,%9}, {%0,%1,%2,%3};"
                : "+f"(c0), "+f"(c1), "+f"(c2), "+f"(c3)
                : "r"(af.x), "r"(af.y), "r"(af.z), "r"(af.w), "r"(pb0[t]), "r"(pb1[t]));
        }
        __syncwarp();
        if (lane == 0) asm volatile("fence.proxy.async.shared::cta;" ::: "memory");
        ISSUE(g + NST);
    }
#undef ISSUE

    __syncthreads();      // all warps done consuming the E ring: safe to alias sacc
    {
        int r = lane >> 2, cc = (lane & 3) * 2;
        float* sw = sacc + w * 128;
        sw[r * 8 + cc]           = c0;
        sw[r * 8 + cc + 1]       = c1;
        sw[(r + 8) * 8 + cc]     = c2;
        sw[(r + 8) * 8 + cc + 1] = c3;
    }
    __syncthreads();

    if (tid < 64) {
        int rr = tid >> 2, b = tid & 3;
        float v = 0.f;
#pragma unroll
        for (int kw = 0; kw < 8; kw++) v += sacc[kw * 128 + rr * 8 + b];
        int row = rt * 16 + rr;
        float y = fmaf(0.999f, thin[row * 4 + b], v);
        const float* bmr = Bm + (size_t)row * 17;
#pragma unroll
        for (int c = 0; c < 17; c++) y = fmaf(bmr[c], sdiff[c * 4 + b], y);
        g_theta[(i + 1) & 1][row * 4 + b] = y;
        g_thh[(i + 1) & 1][b][row] = __float2half(y);
    }
}

// ---------------- final root for step T-1 ----------------
__global__ void root_final(const float* __restrict__ ts, float* __restrict__ out) {
    __shared__ float rh[2][4][64];
    PDL_WAIT();
    root_apply(Tt - 1, g_theta[Tt & 1], ts, out, &rh[0][0][0], &rh[1][0][0]);
}

// ---------------- launch ----------------
extern "C" void kernel_launch(void* const* d_in, const int* in_sizes, int n_in,
                              void* d_out, int out_size) {
    const float* xs = (const float*)d_in[0];
    const float* ts = (const float*)d_in[1];
    const float* A  = (const float*)d_in[2];
    const float* Bm = (const float*)d_in[3];
    const float* W1 = (const float*)d_in[4];
    const float* b1 = (const float*)d_in[5];
    const float* W2 = (const float*)d_in[6];
    const float* b2 = (const float*)d_in[7];
    const float* W3 = (const float*)d_in[8];
    const float* b3 = (const float*)d_in[9];
    // d_in[10] = seed: dead (FORCING_PROB == 1.0)
    float* out = (float*)d_out;

    static bool attr_done = false;
    if (!attr_done) {
        cudaFuncSetAttribute(step_kernel, cudaFuncAttributeMaxDynamicSharedMemorySize, SM_DYN);
        attr_done = true;
    }

    void *p_h1, *p_h2, *p_th;
    cudaGetSymbolAddress(&p_h1, g_h1);
    cudaGetSymbolAddress(&p_h2, g_h2);
    cudaGetSymbolAddress(&p_th, g_theta);   // g_theta[0]

    size_t npk = (size_t)NT * NT * 32;
    cvt_E_pack<<<(unsigned)((npk + 255) / 256), 256>>>(A);

    mlp1_kernel<<<(H1n * 4 + 255) / 256, 256>>>(W1, b1, xs);
    matvec4<<<(H2n * 32 + 255) / 256, 256>>>(W2, b2, (const float*)p_h1, (float*)p_h2, H2n, H1n, 1, 0);
    matvec4<<<((size_t)Ln * 32 + 255) / 256, 256>>>(W3, b3, (const float*)p_h2, (float*)p_th, Ln, H2n, 0, 1);

    // PDL-chained step kernels: preamble of step i+1 overlaps tail of step i
    cudaLaunchAttribute at[1];
    at[0].id = cudaLaunchAttributeProgrammaticStreamSerialization;
    at[0].val.programmaticStreamSerializationAllowed = 1;

    cudaLaunchConfig_t cfg = {};
    cfg.gridDim = dim3(399);
    cfg.blockDim = dim3(256);
    cfg.dynamicSmemBytes = SM_DYN;
    cfg.stream = 0;
    cfg.attrs = at;
    cfg.numAttrs = 1;

    for (int i = 0; i < Tt; i++)
        cudaLaunchKernelEx(&cfg, step_kernel, i, xs, ts, Bm, out);

    cudaLaunchConfig_t cfgr = {};
    cfgr.gridDim = dim3(1);
    cfgr.blockDim = dim3(256);
    cfgr.dynamicSmemBytes = 0;
    cfgr.stream = 0;
    cfgr.attrs = at;
    cfgr.numAttrs = 1;
    cudaLaunchKernelEx(&cfgr, root_final, ts, out);
}

// round 15
// speedup vs baseline: 1.0697x; 1.0031x over previous
#include <cuda_runtime.h>
#include <cuda_fp16.h>
#include <cstdint>

#define Ln    6368
#define Tt    128
#define H1n   2133
#define H2n   4250
#define NT    398          // 16-row tiles: 6368/16
#define TPW   50           // k-tiles per warp (warp 7 gets 48)
#define CgT   5            // fragment-tiles per TMA group (2560 B)
#define NGRP  10           // groups per warp
#define NST   3            // ring stages
#define THS   6376         // padded theta smem stride (halves) -> conflict-free LDS

// dynamic smem layout (bytes)
#define SM_TH    0                         // fp16 theta 4*THS*2 = 51008 (slot 51200)
#define SM_EBUF  51200                     // 8 warps * 3 stages * 2560 = 61440
#define SM_MBAR  (51200 + 61440)           // 24 E mbars + 1 theta mbar (256)
#define SM_SDIFF (SM_MBAR + 256)           // 272 (pad 288)
#define SM_DYN   (SM_SDIFF + 288)          // 113184
// sacc (4KB) aliases SM_EBUF after the mainloop; root scratch aliases SM_EBUF in block 0.

// ---------------- device state ----------------
__device__ __align__(16) uint4  g_Epk[(size_t)NT * NT * 32];   // E fragments, 81 MB
__device__ __align__(16) float  g_theta[2][Ln * 4];            // fp32 theta [j][b]
__device__ __align__(16) __half g_thh[2][4][Ln];               // fp16 theta [b][j]
__device__ __align__(16) float  g_h1[H1n * 4];
__device__ __align__(16) float  g_h2[H2n * 4];
__device__ __align__(16) float  g_xhat[Tt][4][16];

// ---------------- helpers ----------------
__device__ __forceinline__ uint32_t s2u(const void* p) {
    uint32_t a;
    asm("{ .reg .u64 t; cvta.to.shared.u64 t, %1; cvt.u32.u64 %0, t; }" : "=r"(a) : "l"(p));
    return a;
}
#define MBAR_INIT(a, n) asm volatile("mbarrier.init.shared.b64 [%0], %1;" :: "r"(a), "r"(n) : "memory")
#define MBAR_EXPECT(a, b) asm volatile("mbarrier.arrive.expect_tx.shared.b64 _, [%0], %1;" :: "r"(a), "r"(b) : "memory")
#define MBAR_WAIT(a, p) asm volatile( \
    "{\n\t.reg .pred P1;\nWL_%=:\n\t" \
    "mbarrier.try_wait.parity.acquire.cta.shared::cta.b64 P1, [%0], %1, 0x989680;\n\t" \
    "@P1 bra.uni WD_%=;\n\tbra.uni WL_%=;\nWD_%=:\n\t}" \
    :: "r"(a), "r"(p) : "memory")
#define BULK_CP(dst, src, bytes, mb) \
    asm volatile("cp.async.bulk.shared::cta.global.mbarrier::complete_tx::bytes [%0], [%1], %2, [%3];" \
                 :: "r"(dst), "l"(src), "r"(bytes), "r"(mb) : "memory")
#define BULK_CP_EL(dst, src, bytes, mb, pol) \
    asm volatile("cp.async.bulk.shared::cta.global.mbarrier::complete_tx::bytes.L2::cache_hint " \
                 "[%0], [%1], %2, [%3], %4;" \
                 :: "r"(dst), "l"(src), "r"(bytes), "r"(mb), "l"(pol) : "memory")
#define PDL_LAUNCH_DEPS() asm volatile("griddepcontrol.launch_dependents;" ::: "memory")
#define PDL_WAIT()        asm volatile("griddepcontrol.wait;" ::: "memory")

// ---------------- E conversion + fragment repack (evict_last stores) ----------------
__global__ void cvt_E_pack(const float* __restrict__ A) {
    size_t idx = (size_t)blockIdx.x * blockDim.x + threadIdx.x;
    if (idx >= (size_t)NT * NT * 32) return;
    int lane = (int)(idx & 31);
    size_t tIdx = idx >> 5;
    int rt = (int)(tIdx / NT), jt = (int)(tIdx % NT);
    int r0 = rt * 16 + (lane >> 2);
    int c0 = jt * 16 + (lane & 3) * 2;
    const float* Ar0 = A + (size_t)r0 * Ln;
    const float* Ar8 = A + (size_t)(r0 + 8) * Ln;
    float2 p00 = *reinterpret_cast<const float2*>(Ar0 + c0);
    float2 p10 = *reinterpret_cast<const float2*>(Ar8 + c0);
    float2 p01 = *reinterpret_cast<const float2*>(Ar0 + c0 + 8);
    float2 p11 = *reinterpret_cast<const float2*>(Ar8 + c0 + 8);
    if (r0 == c0)         p00.x -= 0.999f;
    if (r0 == c0 + 1)     p00.y -= 0.999f;
    if (r0 + 8 == c0)     p10.x -= 0.999f;
    if (r0 + 8 == c0 + 1) p10.y -= 0.999f;
    if (r0 == c0 + 8)     p01.x -= 0.999f;
    if (r0 == c0 + 9)     p01.y -= 0.999f;
    if (r0 + 8 == c0 + 8) p11.x -= 0.999f;
    if (r0 + 8 == c0 + 9) p11.y -= 0.999f;
    __half2 h0 = __floats2half2_rn(p00.x, p00.y);
    __half2 h1 = __floats2half2_rn(p10.x, p10.y);
    __half2 h2 = __floats2half2_rn(p01.x, p01.y);
    __half2 h3 = __floats2half2_rn(p11.x, p11.y);
    uint64_t pol;
    asm("createpolicy.fractional.L2::evict_last.b64 %0, 1.0;" : "=l"(pol));
    asm volatile("st.global.L2::cache_hint.v4.b32 [%0], {%1,%2,%3,%4}, %5;"
                 :: "l"(&g_Epk[idx]),
                    "r"(*reinterpret_cast<unsigned*>(&h0)),
                    "r"(*reinterpret_cast<unsigned*>(&h1)),
                    "r"(*reinterpret_cast<unsigned*>(&h2)),
                    "r"(*reinterpret_cast<unsigned*>(&h3)),
                    "l"(pol) : "memory");
}

// ---------------- init MLP ----------------
__global__ void mlp1_kernel(const float* __restrict__ W1, const float* __restrict__ b1,
                            const float* __restrict__ xs) {
    int t = blockIdx.x * blockDim.x + threadIdx.x;
    if (t >= H1n * 4) return;
    int row = t >> 2, b = t & 3;
    float a = b1[row];
    const float* x0 = xs + (size_t)b * Tt * 16;
#pragma unroll
    for (int d = 0; d < 16; d++) a = fmaf(W1[row * 16 + d], x0[d], a);
    g_h1[row * 4 + b] = fmaxf(a, 0.0f);
}

// warp-per-row fp32 matvec; writeh!=0 also writes fp16-transposed output to g_thh[0]
__global__ void matvec4(const float* __restrict__ W, const float* __restrict__ bias,
                        const float* __restrict__ xin, float* __restrict__ yout,
                        int rows, int K, int relu, int writeh) {
    int w = (blockIdx.x * blockDim.x + threadIdx.x) >> 5;
    int lane = threadIdx.x & 31;
    if (w >= rows) return;
    const float* Wr = W + (size_t)w * K;
    float a0 = 0.f, a1 = 0.f, a2 = 0.f, a3 = 0.f;
#pragma unroll 4
    for (int j = lane; j < K; j += 32) {
        float wv = Wr[j];
        float4 xv = reinterpret_cast<const float4*>(xin)[j];
        a0 = fmaf(wv, xv.x, a0); a1 = fmaf(wv, xv.y, a1);
        a2 = fmaf(wv, xv.z, a2); a3 = fmaf(wv, xv.w, a3);
    }
#pragma unroll
    for (int m = 16; m > 0; m >>= 1) {
        a0 += __shfl_xor_sync(0xffffffffu, a0, m);
        a1 += __shfl_xor_sync(0xffffffffu, a1, m);
        a2 += __shfl_xor_sync(0xffffffffu, a2, m);
        a3 += __shfl_xor_sync(0xffffffffu, a3, m);
    }
    if (lane == 0) {
        float bb = bias[w];
        a0 += bb; a1 += bb; a2 += bb; a3 += bb;
        if (relu) {
            a0 = fmaxf(a0, 0.f); a1 = fmaxf(a1, 0.f);
            a2 = fmaxf(a2, 0.f); a3 = fmaxf(a3, 0.f);
        }
        reinterpret_cast<float4*>(yout)[w] = make_float4(a0, a1, a2, a3);
        if (writeh) {
            g_thh[0][0][w] = __float2half(a0);
            g_thh[0][1][w] = __float2half(a1);
            g_thh[0][2][w] = __float2half(a2);
            g_thh[0][3][w] = __float2half(a3);
        }
    }
}

// ---------------- tiny root MLP (scratch supplied by caller) ----------------
__device__ void root_apply(int j, const float* __restrict__ th,
                           const float* __restrict__ ts, float* __restrict__ out,
                           float* rh0, float* rh1) {          // each [4][64]
    int tid = threadIdx.x;
    int b = tid >> 6, k = tid & 63;
    float tj  = ts[b * Tt + j];
    float tin = (j == 0) ? tj : (2.0f * tj - ts[b * Tt + j - 1]);
    float h = fmaf(th[k * 4 + b], tin, th[(64 + k) * 4 + b]);
    rh0[b * 64 + k] = fmaxf(h, 0.0f);
    __syncthreads();
    float a = th[(4224 + k) * 4 + b];
#pragma unroll 8
    for (int c = 0; c < 64; c++)
        a = fmaf(th[(128 + k * 64 + c) * 4 + b], rh0[b * 64 + c], a);
    rh1[b * 64 + k] = fmaxf(a, 0.0f);
    __syncthreads();
    if (k < 32) {
        float o = th[(6336 + k) * 4 + b];
#pragma unroll 8
        for (int c = 0; c < 64; c++)
            o = fmaf(th[(4288 + k * 64 + c) * 4 + b], rh1[b * 64 + c], o);
        float v;
        if (k < 16) {
            v = tanhf(o);
            g_xhat[j][b][k] = v;
        } else {
            v = fmaxf(o, 0.0f) + log1pf(expf(-fabsf(o)));
        }
        out[((size_t)b * Tt + j) * 32 + k] = v;
    }
}

// ---------------- per-step kernel (PDL + 3-stage E ring + TMA theta) ----------------
__global__ void __launch_bounds__(256, 2) step_kernel(int i, const float* __restrict__ xs,
                                                      const float* __restrict__ ts,
                                                      const float* __restrict__ Bm,
                                                      float* __restrict__ out) {
    extern __shared__ __align__(1024) char dsm[];
    if (blockIdx.x == 0) {
        if (threadIdx.x == 0) PDL_LAUNCH_DEPS();
        PDL_WAIT();
        if (i >= 1)
            root_apply(i - 1, g_theta[i & 1], ts, out,
                       reinterpret_cast<float*>(dsm + SM_EBUF),
                       reinterpret_cast<float*>(dsm + SM_EBUF + 1024));
        return;
    }
    __half* th_s = reinterpret_cast<__half*>(dsm);
    float* sdiff = reinterpret_cast<float*>(dsm + SM_SDIFF);    // [17][4]
    float* sacc  = reinterpret_cast<float*>(dsm + SM_EBUF);     // [8][16][8], aliased post-loop
    uint32_t smem_base = s2u(dsm);
    uint32_t mbar_base = smem_base + SM_MBAR;
    uint32_t tbar = mbar_base + 24 * 8;

    int tid = threadIdx.x, lane = tid & 31, w = tid >> 5;
    int rt = blockIdx.x - 1;
    int jt0 = w * TPW;
    int jtN = min(TPW, NT - jt0);                 // 50 (warp 7: 48)
    int ngroups = NGRP;

    uint32_t mybar = mbar_base + w * (NST * 8);
    uint32_t mybuf = smem_base + SM_EBUF + w * (NST * CgT * 512);
    const char* esrc = reinterpret_cast<const char*>(g_Epk) + ((size_t)rt * NT + jt0) * 512;

    uint64_t pol;
    asm("createpolicy.fractional.L2::evict_last.b64 %0, 1.0;" : "=l"(pol));

    // ---- pre-wait preamble: mbar init + E prefetch (independent of theta) ----
    if (tid < 25) MBAR_INIT(mbar_base + tid * 8, 1);
    __syncthreads();
    if (tid == 0) asm volatile("fence.proxy.async.shared::cta;" ::: "memory");
    __syncthreads();

#define ISSUE(g) do { \
        int _g = (g); \
        if (_g < ngroups && lane == 0) { \
            int _t0 = _g * CgT; \
            unsigned _bytes = (unsigned)(min(CgT, jtN - _t0) * 512); \
            int _s = _g % NST; \
            MBAR_EXPECT(mybar + _s * 8, _bytes); \
            BULK_CP_EL(mybuf + _s * (CgT * 512), esrc + (size_t)_t0 * 512, _bytes, mybar + _s * 8, pol); \
        } \
    } while (0)

    ISSUE(0); ISSUE(1); ISSUE(2);
    if (tid == 0) PDL_LAUNCH_DEPS();

    // ---- wait for predecessor step (theta/xhat now visible) ----
    PDL_WAIT();

    const float* thin = g_theta[i & 1];

    // stage fp16 theta via 4 bulk copies into the padded smem stride
    if (tid == 0) {
        MBAR_EXPECT(tbar, 4 * Ln * 2);
#pragma unroll
        for (int b = 0; b < 4; b++)
            BULK_CP(smem_base + SM_TH + b * (THS * 2),
                    reinterpret_cast<const char*>(&g_thh[i & 1][b][0]), Ln * 2, tbar);
    }
    if (tid < 68) {
        int c = tid >> 2, b = tid & 3;
        float d;
        if (c == 0) {
            d = (i == 0) ? 0.0f : ts[b * Tt + i] - ts[b * Tt + i - 1];
        } else {
            float xt = xs[((size_t)b * Tt + i) * 16 + (c - 1)];
            float xp = (i < 2) ? xs[(size_t)b * Tt * 16 + (c - 1)]
                               : g_xhat[i - 2][b][c - 1];
            d = xt - xp;
        }
        sdiff[c * 4 + b] = d;
    }
    __syncthreads();

    int n = lane >> 2, k0 = (lane & 3) * 2;
    const __half* bn = th_s + n * THS;
    bool bvalid = (n < 4);

    MBAR_WAIT(tbar, 0);   // theta resident in smem

    float c0 = 0.f, c1 = 0.f, c2 = 0.f, c3 = 0.f;
    for (int g = 0; g < ngroups; g++) {
        int t0 = g * CgT;
        int nt = min(CgT, jtN - t0);
        // prefetch B fragments (smem theta, independent of E TMA) before the wait
        unsigned pb0[CgT], pb1[CgT];
#pragma unroll
        for (int t = 0; t < CgT; t++) {
            pb0[t] = 0u; pb1[t] = 0u;
            if (bvalid && t < nt) {
                int jj = (jt0 + t0 + t) * 16 + k0;
                pb0[t] = *reinterpret_cast<const unsigned*>(bn + jj);
                pb1[t] = *reinterpret_cast<const unsigned*>(bn + jj + 8);
            }
        }
        int s = g % NST, ph = (g / NST) & 1;
        MBAR_WAIT(mybar + s * 8, ph);
        uint32_t bufb = mybuf + s * (CgT * 512) + lane * 16;
#pragma unroll
        for (int t = 0; t < CgT; t++) {
            if (t >= nt) break;
            uint4 af;
            asm volatile("ld.shared.v4.u32 {%0,%1,%2,%3}, [%4];"
                         : "=r"(af.x), "=r"(af.y), "=r"(af.z), "=r"(af.w)
                         : "r"(bufb + t * 512));
            asm volatile(
                "mma.sync.aligned.m16n8k16.row.col.f32.f16.f16.f32 "
                "{%0,%1,%2,%3}, {%4,%5,%6,%7}, {%8,%9}, {%0,%1,%2,%3};"
                : "+f"(c0), "+f"(c1), "+f"(c2), "+f"(c3)
                : "r"(af.x), "r"(af.y), "r"(af.z), "r"(af.w), "r"(pb0[t]), "r"(pb1[t]));
        }
        __syncwarp();
        if (lane == 0) asm volatile("fence.proxy.async.shared::cta;" ::: "memory");
        ISSUE(g + NST);
    }
#undef ISSUE

    __syncthreads();      // all warps done consuming the E ring: safe to alias sacc
    {
        int r = lane >> 2, cc = (lane & 3) * 2;
        float* sw = sacc + w * 128;
        sw[r * 8 + cc]           = c0;
        sw[r * 8 + cc + 1]       = c1;
        sw[(r + 8) * 8 + cc]     = c2;
        sw[(r + 8) * 8 + cc + 1] = c3;
    }
    __syncthreads();

    if (tid < 64) {
        int rr = tid >> 2, b = tid & 3;
        float v = 0.f;
#pragma unroll
        for (int kw = 0; kw < 8; kw++) v += sacc[kw * 128 + rr * 8 + b];
        int row = rt * 16 + rr;
        float y = fmaf(0.999f, thin[row * 4 + b], v);
        const float* bmr = Bm + (size_t)row * 17;
#pragma unroll
        for (int c = 0; c < 17; c++) y = fmaf(bmr[c], sdiff[c * 4 + b], y);
        g_theta[(i + 1) & 1][row * 4 + b] = y;
        g_thh[(i + 1) & 1][b][row] = __float2half(y);
    }
}

// ---------------- final root for step T-1 ----------------
__global__ void root_final(const float* __restrict__ ts, float* __restrict__ out) {
    __shared__ float rh[2][4][64];
    PDL_WAIT();
    root_apply(Tt - 1, g_theta[Tt & 1], ts, out, &rh[0][0][0], &rh[1][0][0]);
}

// ---------------- launch ----------------
extern "C" void kernel_launch(void* const* d_in, const int* in_sizes, int n_in,
                              void* d_out, int out_size) {
    const float* xs = (const float*)d_in[0];
    const float* ts = (const float*)d_in[1];
    const float* A  = (const float*)d_in[2];
    const float* Bm = (const float*)d_in[3];
    const float* W1 = (const float*)d_in[4];
    const float* b1 = (const float*)d_in[5];
    const float* W2 = (const float*)d_in[6];
    const float* b2 = (const float*)d_in[7];
    const float* W3 = (const float*)d_in[8];
    const float* b3 = (const float*)d_in[9];
    // d_in[10] = seed: dead (FORCING_PROB == 1.0)
    float* out = (float*)d_out;

    static bool attr_done = false;
    if (!attr_done) {
        cudaFuncSetAttribute(step_kernel, cudaFuncAttributeMaxDynamicSharedMemorySize, SM_DYN);
        attr_done = true;
    }

    void *p_h1, *p_h2, *p_th;
    cudaGetSymbolAddress(&p_h1, g_h1);
    cudaGetSymbolAddress(&p_h2, g_h2);
    cudaGetSymbolAddress(&p_th, g_theta);   // g_theta[0]

    size_t npk = (size_t)NT * NT * 32;
    cvt_E_pack<<<(unsigned)((npk + 255) / 256), 256>>>(A);

    mlp1_kernel<<<(H1n * 4 + 255) / 256, 256>>>(W1, b1, xs);
    matvec4<<<(H2n * 32 + 255) / 256, 256>>>(W2, b2, (const float*)p_h1, (float*)p_h2, H2n, H1n, 1, 0);
    matvec4<<<((size_t)Ln * 32 + 255) / 256, 256>>>(W3, b3, (const float*)p_h2, (float*)p_th, Ln, H2n, 0, 1);

    // PDL-chained step kernels: preamble of step i+1 overlaps tail of step i
    cudaLaunchAttribute at[1];
    at[0].id = cudaLaunchAttributeProgrammaticStreamSerialization;
    at[0].val.programmaticStreamSerializationAllowed = 1;

    cudaLaunchConfig_t cfg = {};
    cfg.gridDim = dim3(399);
    cfg.blockDim = dim3(256);
    cfg.dynamicSmemBytes = SM_DYN;
    cfg.stream = 0;
    cfg.attrs = at;
    cfg.numAttrs = 1;

    for (int i = 0; i < Tt; i++)
        cudaLaunchKernelEx(&cfg, step_kernel, i, xs, ts, Bm, out);

    cudaLaunchConfig_t cfgr = {};
    cfgr.gridDim = dim3(1);
    cfgr.blockDim = dim3(256);
    cfgr.dynamicSmemBytes = 0;
    cfgr.stream = 0;
    cfgr.attrs = at;
    cfgr.numAttrs = 1;
    cudaLaunchKernelEx(&cfgr, root_final, ts, out);
}